// round 3
// baseline (speedup 1.0000x reference)
#include <cuda_runtime.h>

// ---------------------------------------------------------------------------
// LeNet-5 forward, B=8192, fp32.
// Stages:
//   prep : build pooled-effective 6x6 filters (conv5x5 + avgpool2x2 fused),
//          fold S2/S4 affine + 2/3 slope into weights/bias.
//   K1   : C1+S2+act   -> A[8192][6][16][16]
//   K2   : C3+S4+act   -> B[8192][16][6][6]    (sparse connectivity bitmask)
//   K3   : C5 (+bias)  -> C[8192][480]  (== [32768][120] after reshape)
//   K4   : F6+act+RBF  -> out[32768][10]   (SLOPE folded into F6 W/b)
// ---------------------------------------------------------------------------

#define ACT_SCALE 1.7159f
#define ACT_SLOPE (2.0f / 3.0f)

// bit i of c_cmask[o] set iff input channel i feeds output channel o (MAP_INFO)
static __constant__ unsigned c_cmask[16] = {
    7u, 14u, 28u, 56u, 49u, 35u, 15u, 30u,
    60u, 57u, 51u, 39u, 27u, 54u, 45u, 63u
};

// Scratch (module-static device memory; no runtime allocation)
__device__ float g_A[8192 * 6 * 16 * 16];   // 50.3 MB
__device__ float g_B[8192 * 16 * 6 * 6];    // 18.9 MB
__device__ float g_C[8192 * 480];           // 15.7 MB
__device__ float g_w6c1[6 * 36];
__device__ float g_bf1[6];
__device__ float g_w6c3[16 * 6 * 36];
__device__ float g_bf3[16];

// ---------------------------------------------------------------------------
// prep: effective pooled filters.
// pooled(i,j) = 1/4 sum_{di,dj in {0,1}} conv5x5 at (2i+di, 2j+dj)
//            = sum_{a,b<6} w6[a][b] * in[2i+a][2j+b]
// w6[a][b] = 1/4 sum_{di,dj} w[a-di][b-dj]  (valid indices only)
// Then fold: act(SLOPE*(s_w*(pooled + conv_b) + s_b))
//   -> weights *= SLOPE*s_w ; bias = SLOPE*(s_w*conv_b + s_b)
// ---------------------------------------------------------------------------
__global__ void k_prep(const float* __restrict__ c1_w, const float* __restrict__ c1_b,
                       const float* __restrict__ s2_w, const float* __restrict__ s2_b,
                       const float* __restrict__ c3_w, const float* __restrict__ c3_b,
                       const float* __restrict__ s4_w, const float* __restrict__ s4_b) {
    int t = threadIdx.x;
    // C1 effective filters: [6][6][6]
    for (int idx = t; idx < 216; idx += 256) {
        int c = idx / 36, a = (idx % 36) / 6, b = idx % 6;
        float s = 0.f;
        #pragma unroll
        for (int di = 0; di < 2; di++)
            #pragma unroll
            for (int dj = 0; dj < 2; dj++) {
                int u = a - di, v = b - dj;
                if (u >= 0 && u < 5 && v >= 0 && v < 5)
                    s += c1_w[(c * 5 + u) * 5 + v];
            }
        g_w6c1[idx] = 0.25f * ACT_SLOPE * s2_w[c] * s;
    }
    if (t < 6) g_bf1[t] = ACT_SLOPE * (s2_w[t] * c1_b[t] + s2_b[t]);
    // C3 effective filters: [16][6][6][6], masked by connectivity
    for (int idx = t; idx < 3456; idx += 256) {
        int o = idx / 216;
        int i = (idx % 216) / 36;
        int ab = idx % 36;
        int a = ab / 6, b = ab % 6;
        float s = 0.f;
        #pragma unroll
        for (int di = 0; di < 2; di++)
            #pragma unroll
            for (int dj = 0; dj < 2; dj++) {
                int u = a - di, v = b - dj;
                if (u >= 0 && u < 5 && v >= 0 && v < 5)
                    s += c3_w[((o * 6 + i) * 5 + u) * 5 + v];
            }
        float m = ((c_cmask[o] >> i) & 1u) ? 1.f : 0.f;
        g_w6c3[idx] = m * 0.25f * ACT_SLOPE * s4_w[o] * s;
    }
    if (t < 16) g_bf3[t] = ACT_SLOPE * (s4_w[t] * c3_b[t] + s4_b[t]);
}

// ---------------------------------------------------------------------------
// K1: C1 (replicate pad 2) + S2 pool + act.  One block per image.
// Input x[b][32][32], output A[b][6][16][16].
// ---------------------------------------------------------------------------
__global__ void __launch_bounds__(256) k1(const float* __restrict__ x) {
    __shared__ float sin[36 * 36];
    __shared__ float sw[216];
    __shared__ float sb[6];
    int b = blockIdx.x, t = threadIdx.x;
    const float* xb = x + (long)b * 1024;
    for (int idx = t; idx < 1296; idx += 256) {
        int r = idx / 36, c = idx % 36;
        int sr = min(max(r - 2, 0), 31);
        int sc = min(max(c - 2, 0), 31);
        sin[idx] = xb[sr * 32 + sc];
    }
    if (t < 216) sw[t] = g_w6c1[t];
    if (t < 6) sb[t] = g_bf1[t];
    __syncthreads();
    float* Ab = g_A + (long)b * 1536;
    for (int oi = t; oi < 1536; oi += 256) {
        int c = oi >> 8;
        int p = oi & 255;
        int i = p >> 4, j = p & 15;
        const float* w = sw + c * 36;
        const float* ip = sin + (2 * i) * 36 + 2 * j;
        float acc = 0.f;
        #pragma unroll
        for (int r = 0; r < 6; r++)
            #pragma unroll
            for (int s = 0; s < 6; s++)
                acc = fmaf(w[r * 6 + s], ip[r * 36 + s], acc);
        Ab[oi] = ACT_SCALE * tanhf(acc + sb[c]);
    }
}

// ---------------------------------------------------------------------------
// K2: C3 (masked) + S4 pool + act.  One block per image.
// Input A[b][6][16][16], output B[b][16][6][6].
// ---------------------------------------------------------------------------
__global__ void __launch_bounds__(256) k2() {
    __shared__ float sa[6 * 256];
    __shared__ float sw[3456];
    __shared__ float sb[16];
    int b = blockIdx.x, t = threadIdx.x;
    const float* Ab = g_A + (long)b * 1536;
    for (int idx = t; idx < 1536; idx += 256) sa[idx] = Ab[idx];
    for (int idx = t; idx < 3456; idx += 256) sw[idx] = g_w6c3[idx];
    if (t < 16) sb[t] = g_bf3[t];
    __syncthreads();
    float* Bb = g_B + (long)b * 576;
    for (int oi = t; oi < 576; oi += 256) {
        int o = oi / 36;
        int p = oi % 36;
        int i = p / 6, j = p % 6;
        unsigned m = c_cmask[o];
        const float* wbase = sw + o * 216;
        const float* ibase = sa + (2 * i) * 16 + 2 * j;
        float acc = 0.f;
        for (int ic = 0; ic < 6; ic++) {
            if (!((m >> ic) & 1u)) continue;
            const float* w = wbase + ic * 36;
            const float* ip = ibase + ic * 256;
            #pragma unroll
            for (int r = 0; r < 6; r++)
                #pragma unroll
                for (int s = 0; s < 6; s++)
                    acc = fmaf(w[r * 6 + s], ip[r * 16 + s], acc);
        }
        Bb[oi] = ACT_SCALE * tanhf(acc + sb[o]);
    }
}

// ---------------------------------------------------------------------------
// K3: C5 16->120 conv5x5 on 6x6 -> [2,2] positions (+bias).
// 32 images per block, weight chunks of 32 channels in smem.
// Thread tile: 4 positions x 4 channels (register-blocked).
// Output C[b][ch*4 + pi*2 + pj].
// Last chunk (96..127) is guarded: channels >= 120 load zero weights and are
// never written back.
// ---------------------------------------------------------------------------
#define K3_IMG 32
#define K3_CH  32
#define K3_INSTRIDE 584   // 576 padded (+8) to spread image rows across banks
#define K3_WSTRIDE  401   // 400 padded (+1)
#define K3_SMEM ((K3_IMG * K3_INSTRIDE + K3_CH * K3_WSTRIDE) * 4)

__global__ void __launch_bounds__(256) k3(const float* __restrict__ c5_w,
                                          const float* __restrict__ c5_b) {
    extern __shared__ float sm3[];
    float* sin = sm3;                         // [32][584]
    float* swt = sm3 + K3_IMG * K3_INSTRIDE;  // [32][401]
    int t = threadIdx.x, blk = blockIdx.x;
    const float* Bb = g_B + (long)blk * K3_IMG * 576;
    for (int idx = t; idx < K3_IMG * 576; idx += 256) {
        int im = idx / 576, off = idx % 576;
        sin[im * K3_INSTRIDE + off] = Bb[idx];
    }
    int cg = t & 7;   // channel group (4 channels each)
    int pg = t >> 3;  // local image index 0..31 (its 4 positions)
    const float* ip = sin + pg * K3_INSTRIDE;

    for (int chunk = 0; chunk < 120; chunk += K3_CH) {
        __syncthreads();
        for (int idx = t; idx < K3_CH * 400; idx += 256) {
            int ch = idx / 400, k = idx % 400;
            float wv = (chunk + ch < 120) ? c5_w[(long)(chunk + ch) * 400 + k] : 0.f;
            swt[ch * K3_WSTRIDE + k] = wv;
        }
        __syncthreads();

        float acc[4][4];
        #pragma unroll
        for (int p = 0; p < 4; p++)
            #pragma unroll
            for (int c = 0; c < 4; c++) acc[p][c] = 0.f;

        const float* wp = swt + (cg * 4) * K3_WSTRIDE;
        for (int ic = 0; ic < 16; ic++) {
            #pragma unroll
            for (int r = 0; r < 5; r++) {
                #pragma unroll
                for (int s = 0; s < 5; s++) {
                    int k = (ic * 5 + r) * 5 + s;
                    int ioff = ic * 36 + r * 6 + s;
                    float w0 = wp[k];
                    float w1 = wp[K3_WSTRIDE + k];
                    float w2 = wp[2 * K3_WSTRIDE + k];
                    float w3 = wp[3 * K3_WSTRIDE + k];
                    #pragma unroll
                    for (int pi = 0; pi < 2; pi++)
                        #pragma unroll
                        for (int pj = 0; pj < 2; pj++) {
                            float v = ip[ioff + pi * 6 + pj];
                            int p = pi * 2 + pj;
                            acc[p][0] = fmaf(v, w0, acc[p][0]);
                            acc[p][1] = fmaf(v, w1, acc[p][1]);
                            acc[p][2] = fmaf(v, w2, acc[p][2]);
                            acc[p][3] = fmaf(v, w3, acc[p][3]);
                        }
                }
            }
        }
        long gimg = (long)blk * K3_IMG + pg;
        #pragma unroll
        for (int cc = 0; cc < 4; cc++) {
            int ch = chunk + cg * 4 + cc;
            if (ch < 120) {
                float bias = c5_b[ch];
                #pragma unroll
                for (int p = 0; p < 4; p++)
                    g_C[gimg * 480 + ch * 4 + p] = acc[p][cc] + bias;
            }
        }
    }
}

// ---------------------------------------------------------------------------
// K4: F6 (120->84) + act + RBF (squared distance to 10 prototypes).
// View C as [32768][120]. 64 rows per block.
// SLOPE is folded into the F6 weights/bias at smem-load time; the activation
// is then ACT_SCALE * tanh(folded_acc).
// ---------------------------------------------------------------------------
#define K4_ROWS 64
#define K4_SMEM ((K4_ROWS * 121 + 120 * 84 + 840 + K4_ROWS * 85 + 84) * 4)

__global__ void __launch_bounds__(256) k4(const float* __restrict__ f6_w,
                                          const float* __restrict__ f6_b,
                                          const float* __restrict__ rbf_w,
                                          float* __restrict__ out) {
    extern __shared__ float sm4[];
    float* srow = sm4;                  // [64][121]
    float* swt  = srow + K4_ROWS * 121; // [120][84]  (k-major, pre-scaled by SLOPE)
    float* srbf = swt + 120 * 84;       // [84][10]
    float* sh   = srbf + 840;           // [64][85]
    float* sb6  = sh + K4_ROWS * 85;    // [84]       (pre-scaled by SLOPE)
    int t = threadIdx.x, blk = blockIdx.x;
    long row0 = (long)blk * K4_ROWS;

    for (int idx = t; idx < K4_ROWS * 120; idx += 256) {
        int r = idx / 120, k = idx % 120;
        srow[r * 121 + k] = g_C[(row0 + r) * 120 + k];
    }
    for (int idx = t; idx < 120 * 84; idx += 256) {
        int k = idx / 84, n = idx % 84;
        swt[idx] = ACT_SLOPE * f6_w[n * 120 + k];   // transpose to k-major + fold slope
    }
    for (int idx = t; idx < 840; idx += 256) srbf[idx] = rbf_w[idx];
    if (t < 84) sb6[t] = ACT_SLOPE * f6_b[t];
    __syncthreads();

    int rg = t >> 4;    // 16 row-groups of 4 rows
    int cl = t & 15;    // column lane: cols cl, cl+16, ...
    float acc[4][6];
    #pragma unroll
    for (int i = 0; i < 4; i++)
        #pragma unroll
        for (int q = 0; q < 6; q++) acc[i][q] = 0.f;

    const float* r0 = srow + (rg * 4 + 0) * 121;
    const float* r1 = srow + (rg * 4 + 1) * 121;
    const float* r2 = srow + (rg * 4 + 2) * 121;
    const float* r3 = srow + (rg * 4 + 3) * 121;
    for (int k = 0; k < 120; k++) {
        float v0 = r0[k], v1 = r1[k], v2 = r2[k], v3 = r3[k];
        const float* wk = swt + k * 84;
        #pragma unroll
        for (int q = 0; q < 6; q++) {
            int n = cl + 16 * q;
            if (n < 84) {
                float w = wk[n];
                acc[0][q] = fmaf(v0, w, acc[0][q]);
                acc[1][q] = fmaf(v1, w, acc[1][q]);
                acc[2][q] = fmaf(v2, w, acc[2][q]);
                acc[3][q] = fmaf(v3, w, acc[3][q]);
            }
        }
    }
    #pragma unroll
    for (int q = 0; q < 6; q++) {
        int n = cl + 16 * q;
        if (n < 84) {
            float bias = sb6[n];
            #pragma unroll
            for (int i = 0; i < 4; i++)
                sh[(rg * 4 + i) * 85 + n] = ACT_SCALE * tanhf(acc[i][q] + bias);
        }
    }
    __syncthreads();

    for (int idx = t; idx < K4_ROWS * 10; idx += 256) {
        int r = idx / 10, o = idx % 10;
        const float* hr = sh + r * 85;
        float s = 0.f;
        #pragma unroll 4
        for (int n = 0; n < 84; n++) {
            float d = hr[n] - srbf[n * 10 + o];
            s = fmaf(d, d, s);
        }
        out[(row0 + r) * 10 + o] = s;
    }
}

// ---------------------------------------------------------------------------
extern "C" void kernel_launch(void* const* d_in, const int* in_sizes, int n_in,
                              void* d_out, int out_size) {
    const float* x     = (const float*)d_in[0];
    const float* c1_w  = (const float*)d_in[1];
    const float* c1_b  = (const float*)d_in[2];
    const float* s2_w  = (const float*)d_in[3];
    const float* s2_b  = (const float*)d_in[4];
    const float* c3_w  = (const float*)d_in[5];
    const float* c3_b  = (const float*)d_in[6];
    const float* s4_w  = (const float*)d_in[7];
    const float* s4_b  = (const float*)d_in[8];
    const float* c5_w  = (const float*)d_in[9];
    const float* c5_b  = (const float*)d_in[10];
    const float* f6_w  = (const float*)d_in[11];
    const float* f6_b  = (const float*)d_in[12];
    const float* rbf_w = (const float*)d_in[13];

    cudaFuncSetAttribute(k3, cudaFuncAttributeMaxDynamicSharedMemorySize, K3_SMEM);
    cudaFuncSetAttribute(k4, cudaFuncAttributeMaxDynamicSharedMemorySize, K4_SMEM);

    k_prep<<<1, 256>>>(c1_w, c1_b, s2_w, s2_b, c3_w, c3_b, s4_w, s4_b);
    k1<<<8192, 256>>>(x);
    k2<<<8192, 256>>>();
    k3<<<8192 / K3_IMG, 256, K3_SMEM>>>(c5_w, c5_b);
    k4<<<32768 / K4_ROWS, 256, K4_SMEM>>>(f6_w, f6_b, rbf_w, (float*)d_out);
}

// round 4
// speedup vs baseline: 1.0426x; 1.0426x over previous
#include <cuda_runtime.h>

// ---------------------------------------------------------------------------
// LeNet-5 forward, B=8192, fp32.
//   prep : pooled-effective 6x6 filters (conv5x5+avgpool fused), slopes folded
//   K12  : C1+S2+act then C3+S4+act, 4 images/block, all in smem
//          -> B[8192][16][6][6]
//   K3   : C5 (+bias) -> C[8192][480]  (24 img/block, 2 CTAs/SM)
//   K4   : F6+act+RBF -> out[32768][10]
// ---------------------------------------------------------------------------

#define ACT_SCALE 1.7159f
#define ACT_SLOPE (2.0f / 3.0f)

__device__ __forceinline__ float fast_tanh(float x) {
    // tanh(x) = 1 - 2/(exp(2x)+1); exp via ex2.approx, div via rcp.approx.
    // Saturates correctly: x>>0 -> e=inf -> 1; x<<0 -> e=0 -> -1.
    float e = __expf(2.0f * x);
    return 1.0f - __fdividef(2.0f, e + 1.0f);
}

// bit i of c_cmask[o] set iff input channel i feeds output channel o (MAP_INFO)
static __constant__ unsigned c_cmask[16] = {
    7u, 14u, 28u, 56u, 49u, 35u, 15u, 30u,
    60u, 57u, 51u, 39u, 27u, 54u, 45u, 63u
};

// Scratch (module-static device memory; no runtime allocation)
__device__ float g_B[8192 * 16 * 6 * 6];    // 18.9 MB
__device__ float g_C[8192 * 480];           // 15.7 MB
__device__ float g_w6c1[6 * 36];
__device__ float g_bf1[6];
__device__ float g_w6c3[16 * 6 * 36];
__device__ float g_bf3[16];

// ---------------------------------------------------------------------------
// prep: effective pooled filters (see R1 derivation).
// ---------------------------------------------------------------------------
__global__ void k_prep(const float* __restrict__ c1_w, const float* __restrict__ c1_b,
                       const float* __restrict__ s2_w, const float* __restrict__ s2_b,
                       const float* __restrict__ c3_w, const float* __restrict__ c3_b,
                       const float* __restrict__ s4_w, const float* __restrict__ s4_b) {
    int t = threadIdx.x;
    for (int idx = t; idx < 216; idx += 256) {
        int c = idx / 36, a = (idx % 36) / 6, b = idx % 6;
        float s = 0.f;
        #pragma unroll
        for (int di = 0; di < 2; di++)
            #pragma unroll
            for (int dj = 0; dj < 2; dj++) {
                int u = a - di, v = b - dj;
                if (u >= 0 && u < 5 && v >= 0 && v < 5)
                    s += c1_w[(c * 5 + u) * 5 + v];
            }
        g_w6c1[idx] = 0.25f * ACT_SLOPE * s2_w[c] * s;
    }
    if (t < 6) g_bf1[t] = ACT_SLOPE * (s2_w[t] * c1_b[t] + s2_b[t]);
    for (int idx = t; idx < 3456; idx += 256) {
        int o = idx / 216;
        int i = (idx % 216) / 36;
        int ab = idx % 36;
        int a = ab / 6, b = ab % 6;
        float s = 0.f;
        #pragma unroll
        for (int di = 0; di < 2; di++)
            #pragma unroll
            for (int dj = 0; dj < 2; dj++) {
                int u = a - di, v = b - dj;
                if (u >= 0 && u < 5 && v >= 0 && v < 5)
                    s += c3_w[((o * 6 + i) * 5 + u) * 5 + v];
            }
        float m = ((c_cmask[o] >> i) & 1u) ? 1.f : 0.f;
        g_w6c3[idx] = m * 0.25f * ACT_SLOPE * s4_w[o] * s;
    }
    if (t < 16) g_bf3[t] = ACT_SLOPE * (s4_w[t] * c3_b[t] + s4_b[t]);
}

// ---------------------------------------------------------------------------
// K12: fused C1+S2+act and C3+S4+act.  4 images per block; the intermediate
// A[6][16][16] per image never leaves shared memory.
// ---------------------------------------------------------------------------
#define K12_IMG 4

__global__ void __launch_bounds__(256) k12(const float* __restrict__ x) {
    __shared__ float sin[36 * 36];            // padded input (one image at a time)
    __shared__ float sA[K12_IMG][6 * 256];    // C1+S2 outputs
    __shared__ float sw1[216];
    __shared__ float sb1[6];
    __shared__ float sw3[3456];
    __shared__ float sb3[16];
    int t = threadIdx.x;
    long img0 = (long)blockIdx.x * K12_IMG;

    for (int idx = t; idx < 216; idx += 256) sw1[idx] = g_w6c1[idx];
    for (int idx = t; idx < 3456; idx += 256) sw3[idx] = g_w6c3[idx];
    if (t < 6) sb1[t] = g_bf1[t];
    if (t < 16) sb3[t] = g_bf3[t];

    // Phase 1: per image, load padded input, compute C1+S2+act into sA
    for (int m = 0; m < K12_IMG; m++) {
        const float* xb = x + (img0 + m) * 1024;
        __syncthreads();   // previous image's compute done before overwriting sin
        for (int idx = t; idx < 1296; idx += 256) {
            int r = idx / 36, c = idx % 36;
            int sr = min(max(r - 2, 0), 31);
            int sc = min(max(c - 2, 0), 31);
            sin[idx] = xb[sr * 32 + sc];
        }
        __syncthreads();
        for (int oi = t; oi < 1536; oi += 256) {
            int c = oi >> 8;
            int p = oi & 255;
            int i = p >> 4, j = p & 15;
            const float* w = sw1 + c * 36;
            const float* ip = sin + (2 * i) * 36 + 2 * j;
            float acc = 0.f;
            #pragma unroll
            for (int r = 0; r < 6; r++)
                #pragma unroll
                for (int s = 0; s < 6; s++)
                    acc = fmaf(w[r * 6 + s], ip[r * 36 + s], acc);
            sA[m][oi] = ACT_SCALE * fast_tanh(acc + sb1[c]);
        }
    }
    __syncthreads();

    // Phase 2: C3+S4+act for all 4 images -> g_B
    for (int oi = t; oi < K12_IMG * 576; oi += 256) {
        int m = oi / 576;
        int rem = oi % 576;
        int o = rem / 36;
        int p = rem % 36;
        int i = p / 6, j = p % 6;
        unsigned msk = c_cmask[o];
        const float* wbase = sw3 + o * 216;
        const float* ibase = sA[m] + (2 * i) * 16 + 2 * j;
        float acc = 0.f;
        for (int ic = 0; ic < 6; ic++) {
            if (!((msk >> ic) & 1u)) continue;
            const float* w = wbase + ic * 36;
            const float* ip = ibase + ic * 256;
            #pragma unroll
            for (int r = 0; r < 6; r++)
                #pragma unroll
                for (int s = 0; s < 6; s++)
                    acc = fmaf(w[r * 6 + s], ip[r * 16 + s], acc);
        }
        g_B[(img0 + m) * 576 + rem] = ACT_SCALE * fast_tanh(acc + sb3[o]);
    }
}

// ---------------------------------------------------------------------------
// K3: C5 16->120 conv5x5 on 6x6 -> [2,2] positions (+bias).
// 24 images per block (192 threads), weight chunks of 32 channels in smem.
// Thread tile: 4 positions x 4 channels.  smem 107.4 KB -> 2 CTAs/SM.
// ---------------------------------------------------------------------------
#define K3_IMG 24
#define K3_CH  32
#define K3_THREADS 192
#define K3_INSTRIDE 584   // 576 padded (+8) to spread image rows across banks
#define K3_WSTRIDE  401   // 400 padded (+1)
#define K3_SMEM ((K3_IMG * K3_INSTRIDE + K3_CH * K3_WSTRIDE) * 4)
#define K3_GRID ((8192 + K3_IMG - 1) / K3_IMG)

__global__ void __launch_bounds__(K3_THREADS) k3(const float* __restrict__ c5_w,
                                                 const float* __restrict__ c5_b) {
    extern __shared__ float sm3[];
    float* sin = sm3;                         // [24][584]
    float* swt = sm3 + K3_IMG * K3_INSTRIDE;  // [32][401]
    int t = threadIdx.x, blk = blockIdx.x;
    long imgbase = (long)blk * K3_IMG;
    for (int idx = t; idx < K3_IMG * 576; idx += K3_THREADS) {
        int im = idx / 576, off = idx % 576;
        long gi = imgbase + im;
        sin[im * K3_INSTRIDE + off] = (gi < 8192) ? g_B[gi * 576 + off] : 0.f;
    }
    int cg = t & 7;   // channel group (4 channels each)
    int pg = t >> 3;  // local image index 0..23
    const float* ip = sin + pg * K3_INSTRIDE;
    long gimg = imgbase + pg;

    for (int chunk = 0; chunk < 120; chunk += K3_CH) {
        __syncthreads();
        for (int idx = t; idx < K3_CH * 400; idx += K3_THREADS) {
            int ch = idx / 400, k = idx % 400;
            float wv = (chunk + ch < 120) ? c5_w[(long)(chunk + ch) * 400 + k] : 0.f;
            swt[ch * K3_WSTRIDE + k] = wv;
        }
        __syncthreads();

        float acc[4][4];
        #pragma unroll
        for (int p = 0; p < 4; p++)
            #pragma unroll
            for (int c = 0; c < 4; c++) acc[p][c] = 0.f;

        const float* wp = swt + (cg * 4) * K3_WSTRIDE;
        for (int ic = 0; ic < 16; ic++) {
            #pragma unroll
            for (int r = 0; r < 5; r++) {
                #pragma unroll
                for (int s = 0; s < 5; s++) {
                    int k = (ic * 5 + r) * 5 + s;
                    int ioff = ic * 36 + r * 6 + s;
                    float w0 = wp[k];
                    float w1 = wp[K3_WSTRIDE + k];
                    float w2 = wp[2 * K3_WSTRIDE + k];
                    float w3 = wp[3 * K3_WSTRIDE + k];
                    #pragma unroll
                    for (int pi = 0; pi < 2; pi++)
                        #pragma unroll
                        for (int pj = 0; pj < 2; pj++) {
                            float v = ip[ioff + pi * 6 + pj];
                            int p = pi * 2 + pj;
                            acc[p][0] = fmaf(v, w0, acc[p][0]);
                            acc[p][1] = fmaf(v, w1, acc[p][1]);
                            acc[p][2] = fmaf(v, w2, acc[p][2]);
                            acc[p][3] = fmaf(v, w3, acc[p][3]);
                        }
                }
            }
        }
        if (gimg < 8192) {
            #pragma unroll
            for (int cc = 0; cc < 4; cc++) {
                int ch = chunk + cg * 4 + cc;
                if (ch < 120) {
                    float bias = c5_b[ch];
                    #pragma unroll
                    for (int p = 0; p < 4; p++)
                        g_C[gimg * 480 + ch * 4 + p] = acc[p][cc] + bias;
                }
            }
        }
    }
}

// ---------------------------------------------------------------------------
// K4: F6 (120->84) + act + RBF.  View C as [32768][120]; 64 rows/block.
// SLOPE folded into F6 weights/bias at smem load time.
// ---------------------------------------------------------------------------
#define K4_ROWS 64
#define K4_SMEM ((K4_ROWS * 121 + 120 * 84 + 840 + K4_ROWS * 85 + 84) * 4)

__global__ void __launch_bounds__(256) k4(const float* __restrict__ f6_w,
                                          const float* __restrict__ f6_b,
                                          const float* __restrict__ rbf_w,
                                          float* __restrict__ out) {
    extern __shared__ float sm4[];
    float* srow = sm4;                  // [64][121]
    float* swt  = srow + K4_ROWS * 121; // [120][84]  (k-major, pre-scaled)
    float* srbf = swt + 120 * 84;       // [84][10]
    float* sh   = srbf + 840;           // [64][85]
    float* sb6  = sh + K4_ROWS * 85;    // [84]       (pre-scaled)
    int t = threadIdx.x, blk = blockIdx.x;
    long row0 = (long)blk * K4_ROWS;

    for (int idx = t; idx < K4_ROWS * 120; idx += 256) {
        int r = idx / 120, k = idx % 120;
        srow[r * 121 + k] = g_C[(row0 + r) * 120 + k];
    }
    for (int idx = t; idx < 120 * 84; idx += 256) {
        int k = idx / 84, n = idx % 84;
        swt[idx] = ACT_SLOPE * f6_w[n * 120 + k];
    }
    for (int idx = t; idx < 840; idx += 256) srbf[idx] = rbf_w[idx];
    if (t < 84) sb6[t] = ACT_SLOPE * f6_b[t];
    __syncthreads();

    int rg = t >> 4;
    int cl = t & 15;
    float acc[4][6];
    #pragma unroll
    for (int i = 0; i < 4; i++)
        #pragma unroll
        for (int q = 0; q < 6; q++) acc[i][q] = 0.f;

    const float* r0 = srow + (rg * 4 + 0) * 121;
    const float* r1 = srow + (rg * 4 + 1) * 121;
    const float* r2 = srow + (rg * 4 + 2) * 121;
    const float* r3 = srow + (rg * 4 + 3) * 121;
    for (int k = 0; k < 120; k++) {
        float v0 = r0[k], v1 = r1[k], v2 = r2[k], v3 = r3[k];
        const float* wk = swt + k * 84;
        #pragma unroll
        for (int q = 0; q < 6; q++) {
            int n = cl + 16 * q;
            if (n < 84) {
                float w = wk[n];
                acc[0][q] = fmaf(v0, w, acc[0][q]);
                acc[1][q] = fmaf(v1, w, acc[1][q]);
                acc[2][q] = fmaf(v2, w, acc[2][q]);
                acc[3][q] = fmaf(v3, w, acc[3][q]);
            }
        }
    }
    #pragma unroll
    for (int q = 0; q < 6; q++) {
        int n = cl + 16 * q;
        if (n < 84) {
            float bias = sb6[n];
            #pragma unroll
            for (int i = 0; i < 4; i++)
                sh[(rg * 4 + i) * 85 + n] = ACT_SCALE * fast_tanh(acc[i][q] + bias);
        }
    }
    __syncthreads();

    for (int idx = t; idx < K4_ROWS * 10; idx += 256) {
        int r = idx / 10, o = idx % 10;
        const float* hr = sh + r * 85;
        float s = 0.f;
        #pragma unroll 4
        for (int n = 0; n < 84; n++) {
            float d = hr[n] - srbf[n * 10 + o];
            s = fmaf(d, d, s);
        }
        out[(row0 + r) * 10 + o] = s;
    }
}

// ---------------------------------------------------------------------------
extern "C" void kernel_launch(void* const* d_in, const int* in_sizes, int n_in,
                              void* d_out, int out_size) {
    const float* x     = (const float*)d_in[0];
    const float* c1_w  = (const float*)d_in[1];
    const float* c1_b  = (const float*)d_in[2];
    const float* s2_w  = (const float*)d_in[3];
    const float* s2_b  = (const float*)d_in[4];
    const float* c3_w  = (const float*)d_in[5];
    const float* c3_b  = (const float*)d_in[6];
    const float* s4_w  = (const float*)d_in[7];
    const float* s4_b  = (const float*)d_in[8];
    const float* c5_w  = (const float*)d_in[9];
    const float* c5_b  = (const float*)d_in[10];
    const float* f6_w  = (const float*)d_in[11];
    const float* f6_b  = (const float*)d_in[12];
    const float* rbf_w = (const float*)d_in[13];

    cudaFuncSetAttribute(k3, cudaFuncAttributeMaxDynamicSharedMemorySize, K3_SMEM);
    cudaFuncSetAttribute(k4, cudaFuncAttributeMaxDynamicSharedMemorySize, K4_SMEM);

    k_prep<<<1, 256>>>(c1_w, c1_b, s2_w, s2_b, c3_w, c3_b, s4_w, s4_b);
    k12<<<8192 / K12_IMG, 256>>>(x);
    k3<<<K3_GRID, K3_THREADS, K3_SMEM>>>(c5_w, c5_b);
    k4<<<32768 / K4_ROWS, 256, K4_SMEM>>>(f6_w, f6_b, rbf_w, (float*)d_out);
}

// round 6
// speedup vs baseline: 1.6384x; 1.5715x over previous
#include <cuda_runtime.h>

// ---------------------------------------------------------------------------
// LeNet-5 forward, B=8192, fp32.
//   prep : pooled-effective 6x6 filters (conv5x5+avgpool fused), slopes folded
//   K12  : C1+S2+act then C3+S4+act (dense, masked weights pre-zeroed),
//          4 images/block, register-tiled 2x2 -> B[8192][16][6][6]
//   K3   : C5 (+bias) -> C[8192][480], input patches cached in registers,
//          transposed weight tile in smem
//   K4   : F6+act+RBF -> out[32768][10]
// ---------------------------------------------------------------------------

#define ACT_SCALE 1.7159f
#define ACT_SLOPE (2.0f / 3.0f)

__device__ __forceinline__ float fast_tanh(float x) {
    float e = __expf(2.0f * x);
    return 1.0f - __fdividef(2.0f, e + 1.0f);
}

// bit i of c_cmask[o] set iff input channel i feeds output channel o (MAP_INFO)
static __constant__ unsigned c_cmask[16] = {
    7u, 14u, 28u, 56u, 49u, 35u, 15u, 30u,
    60u, 57u, 51u, 39u, 27u, 54u, 45u, 63u
};

// Scratch (module-static device memory; no runtime allocation)
__device__ float g_B[8192 * 16 * 6 * 6];    // 18.9 MB
__device__ float g_C[8192 * 480];           // 15.7 MB
__device__ __align__(16) float g_w6c1[6 * 36];
__device__ float g_bf1[6];
__device__ __align__(16) float g_w6c3[16 * 6 * 36];
__device__ float g_bf3[16];

// ---------------------------------------------------------------------------
// prep: effective pooled filters (see R1 derivation). Masked C3 weights are 0.
// ---------------------------------------------------------------------------
__global__ void k_prep(const float* __restrict__ c1_w, const float* __restrict__ c1_b,
                       const float* __restrict__ s2_w, const float* __restrict__ s2_b,
                       const float* __restrict__ c3_w, const float* __restrict__ c3_b,
                       const float* __restrict__ s4_w, const float* __restrict__ s4_b) {
    int t = threadIdx.x;
    for (int idx = t; idx < 216; idx += 256) {
        int c = idx / 36, a = (idx % 36) / 6, b = idx % 6;
        float s = 0.f;
        #pragma unroll
        for (int di = 0; di < 2; di++)
            #pragma unroll
            for (int dj = 0; dj < 2; dj++) {
                int u = a - di, v = b - dj;
                if (u >= 0 && u < 5 && v >= 0 && v < 5)
                    s += c1_w[(c * 5 + u) * 5 + v];
            }
        g_w6c1[idx] = 0.25f * ACT_SLOPE * s2_w[c] * s;
    }
    if (t < 6) g_bf1[t] = ACT_SLOPE * (s2_w[t] * c1_b[t] + s2_b[t]);
    for (int idx = t; idx < 3456; idx += 256) {
        int o = idx / 216;
        int i = (idx % 216) / 36;
        int ab = idx % 36;
        int a = ab / 6, b = ab % 6;
        float s = 0.f;
        #pragma unroll
        for (int di = 0; di < 2; di++)
            #pragma unroll
            for (int dj = 0; dj < 2; dj++) {
                int u = a - di, v = b - dj;
                if (u >= 0 && u < 5 && v >= 0 && v < 5)
                    s += c3_w[((o * 6 + i) * 5 + u) * 5 + v];
            }
        float m = ((c_cmask[o] >> i) & 1u) ? 1.f : 0.f;
        g_w6c3[idx] = m * 0.25f * ACT_SLOPE * s4_w[o] * s;
    }
    if (t < 16) g_bf3[t] = ACT_SLOPE * (s4_w[t] * c3_b[t] + s4_b[t]);
}

// ---------------------------------------------------------------------------
// K12: fused C1+S2+act and C3+S4+act.  4 images/block, 192 threads.
// C1: thread = (img, ch) with weights in regs; 8 tiles of 2x2 outputs each.
// C3: thread = (img, och), dense over 6 in-ch; 3 tiles of 2x2 outputs each.
// ---------------------------------------------------------------------------
#define K12_IMG 4
#define K12_THREADS 192

__global__ void __launch_bounds__(K12_THREADS) k12(const float* __restrict__ x) {
    __shared__ __align__(16) float sin[K12_IMG][1296];   // padded 36x36 inputs
    __shared__ __align__(16) float sA[K12_IMG][1536];    // C1+S2 outputs [6][16][16]
    __shared__ __align__(16) float sw1[216];
    __shared__ __align__(16) float sw3[3456];
    __shared__ float sb1[6];
    __shared__ float sb3[16];
    int t = threadIdx.x;
    long img0 = (long)blockIdx.x * K12_IMG;

    for (int idx = t; idx < 216; idx += K12_THREADS) sw1[idx] = g_w6c1[idx];
    for (int idx = t; idx < 3456; idx += K12_THREADS) sw3[idx] = g_w6c3[idx];
    if (t < 6) sb1[t] = g_bf1[t];
    if (t < 16) sb3[t] = g_bf3[t];
    for (int idx = t; idx < K12_IMG * 1296; idx += K12_THREADS) {
        int m = idx / 1296, p = idx % 1296;
        int r = p / 36, c = p % 36;
        int sr = min(max(r - 2, 0), 31);
        int sc = min(max(c - 2, 0), 31);
        sin[m][p] = x[(img0 + m) * 1024 + sr * 32 + sc];
    }
    __syncthreads();

    // ---- C1+S2+act ----
    {
        int pr = t >> 3;          // 0..23 = img*6 + ch
        int q = t & 7;
        int img = pr / 6, ch = pr % 6;
        float4 w4[9];
        float* w = (float*)w4;
        #pragma unroll
        for (int v = 0; v < 9; v++)
            w4[v] = ((const float4*)(sw1 + ch * 36))[v];
        float bias = sb1[ch];
        #pragma unroll
        for (int tl = 0; tl < 8; tl++) {
            // tile = q + tl*8  ->  ti = tl, tj = q
            const float* bp = &sin[img][0] + (4 * tl) * 36 + 4 * q;
            float a00 = 0.f, a01 = 0.f, a10 = 0.f, a11 = 0.f;
            #pragma unroll
            for (int row = 0; row < 8; row++) {
                float2 rv2[4];
                float* rv = (float*)rv2;
                #pragma unroll
                for (int h = 0; h < 4; h++)
                    rv2[h] = *(const float2*)(bp + row * 36 + 2 * h);
                if (row < 6) {
                    #pragma unroll
                    for (int s = 0; s < 6; s++) {
                        float wv = w[row * 6 + s];
                        a00 = fmaf(wv, rv[s], a00);
                        a01 = fmaf(wv, rv[2 + s], a01);
                    }
                }
                if (row >= 2) {
                    #pragma unroll
                    for (int s = 0; s < 6; s++) {
                        float wv = w[(row - 2) * 6 + s];
                        a10 = fmaf(wv, rv[s], a10);
                        a11 = fmaf(wv, rv[2 + s], a11);
                    }
                }
            }
            float* op = &sA[img][ch * 256 + (2 * tl) * 16 + 2 * q];
            op[0]  = ACT_SCALE * fast_tanh(a00 + bias);
            op[1]  = ACT_SCALE * fast_tanh(a01 + bias);
            op[16] = ACT_SCALE * fast_tanh(a10 + bias);
            op[17] = ACT_SCALE * fast_tanh(a11 + bias);
        }
    }
    __syncthreads();

    // ---- C3+S4+act (dense; masked weights are zero) ----
    {
        int pr = t / 3;           // 0..63 = img*16 + och
        int q = t % 3;
        int img = pr >> 4, och = pr & 15;
        float bias = sb3[och];
        float acc[3][4];
        #pragma unroll
        for (int u = 0; u < 3; u++)
            #pragma unroll
            for (int v = 0; v < 4; v++) acc[u][v] = 0.f;
        int ti_[3], tj_[3];
        #pragma unroll
        for (int u = 0; u < 3; u++) {
            int tile = q + u * 3;       // 0..8
            ti_[u] = tile / 3;
            tj_[u] = tile % 3;
        }
        for (int ic = 0; ic < 6; ic++) {
            float4 w4[9];
            float* w = (float*)w4;
            #pragma unroll
            for (int v = 0; v < 9; v++)
                w4[v] = ((const float4*)(sw3 + och * 216 + ic * 36))[v];
            #pragma unroll
            for (int u = 0; u < 3; u++) {
                const float* bp = &sA[img][ic * 256 + (4 * ti_[u]) * 16 + 4 * tj_[u]];
                #pragma unroll
                for (int row = 0; row < 8; row++) {
                    float2 rv2[4];
                    float* rv = (float*)rv2;
                    #pragma unroll
                    for (int h = 0; h < 4; h++)
                        rv2[h] = *(const float2*)(bp + row * 16 + 2 * h);
                    if (row < 6) {
                        #pragma unroll
                        for (int s = 0; s < 6; s++) {
                            float wv = w[row * 6 + s];
                            acc[u][0] = fmaf(wv, rv[s], acc[u][0]);
                            acc[u][1] = fmaf(wv, rv[2 + s], acc[u][1]);
                        }
                    }
                    if (row >= 2) {
                        #pragma unroll
                        for (int s = 0; s < 6; s++) {
                            float wv = w[(row - 2) * 6 + s];
                            acc[u][2] = fmaf(wv, rv[s], acc[u][2]);
                            acc[u][3] = fmaf(wv, rv[2 + s], acc[u][3]);
                        }
                    }
                }
            }
        }
        float* ob = g_B + (img0 + img) * 576 + och * 36;
        #pragma unroll
        for (int u = 0; u < 3; u++) {
            int r0 = 2 * ti_[u], c0 = 2 * tj_[u];
            ob[r0 * 6 + c0]           = ACT_SCALE * fast_tanh(acc[u][0] + bias);
            ob[r0 * 6 + c0 + 1]       = ACT_SCALE * fast_tanh(acc[u][1] + bias);
            ob[(r0 + 1) * 6 + c0]     = ACT_SCALE * fast_tanh(acc[u][2] + bias);
            ob[(r0 + 1) * 6 + c0 + 1] = ACT_SCALE * fast_tanh(acc[u][3] + bias);
        }
    }
}

// ---------------------------------------------------------------------------
// K3: C5 16->120 conv5x5 on 6x6 -> [2,2] positions (+bias).
// 24 images/block (192 threads).  Weight chunk of 32 channels transposed in
// smem as [400][33] (pad 33 -> conflict-free).  Per in-channel the 6x6 input
// patch is cached in registers (9 LDS.128), then 25 k-steps of 16 FMAs.
// ---------------------------------------------------------------------------
#define K3_IMG 24
#define K3_CH  32
#define K3_THREADS 192
#define K3_INSTRIDE 584
#define K3_WSTRIDE  33
#define K3_SMEM ((K3_IMG * K3_INSTRIDE + 400 * K3_WSTRIDE) * 4)
#define K3_GRID ((8192 + K3_IMG - 1) / K3_IMG)

__global__ void __launch_bounds__(K3_THREADS) k3(const float* __restrict__ c5_w,
                                                 const float* __restrict__ c5_b) {
    extern __shared__ __align__(16) float sm3[];
    float* sin = sm3;                         // [24][584]
    float* swt = sm3 + K3_IMG * K3_INSTRIDE;  // [400][33] (k-major, ch minor)
    int t = threadIdx.x;
    long imgbase = (long)blockIdx.x * K3_IMG;
    for (int idx = t; idx < K3_IMG * 576; idx += K3_THREADS) {
        int im = idx / 576, off = idx % 576;
        long gi = imgbase + im;
        sin[im * K3_INSTRIDE + off] = (gi < 8192) ? g_B[gi * 576 + off] : 0.f;
    }
    int cg = t & 7;   // channel group (4 channels each)
    int pg = t >> 3;  // local image index 0..23
    const float* ip = sin + pg * K3_INSTRIDE;
    long gimg = imgbase + pg;
    float* outp = g_C + gimg * 480;

    for (int chunk = 0; chunk < 120; chunk += K3_CH) {
        __syncthreads();
        for (int idx = t; idx < K3_CH * 400; idx += K3_THREADS) {
            int ch = idx / 400, k = idx % 400;   // coalesced gmem read
            float wv = (chunk + ch < 120) ? c5_w[(long)(chunk + ch) * 400 + k] : 0.f;
            swt[k * K3_WSTRIDE + ch] = wv;       // conflict-free (33 is odd)
        }
        __syncthreads();

        float acc[4][4];
        #pragma unroll
        for (int p = 0; p < 4; p++)
            #pragma unroll
            for (int c = 0; c < 4; c++) acc[p][c] = 0.f;

        for (int ic = 0; ic < 16; ic++) {
            float4 pv4[9];
            float* pv = (float*)pv4;
            #pragma unroll
            for (int v = 0; v < 9; v++)
                pv4[v] = ((const float4*)(ip + ic * 36))[v];
            #pragma unroll
            for (int r = 0; r < 5; r++) {
                #pragma unroll
                for (int s = 0; s < 5; s++) {
                    const float* wk = swt + (ic * 25 + r * 5 + s) * K3_WSTRIDE + cg * 4;
                    float w0 = wk[0], w1 = wk[1], w2 = wk[2], w3 = wk[3];
                    #pragma unroll
                    for (int pi = 0; pi < 2; pi++)
                        #pragma unroll
                        for (int pj = 0; pj < 2; pj++) {
                            float v = pv[(pi + r) * 6 + pj + s];
                            int p = pi * 2 + pj;
                            acc[p][0] = fmaf(v, w0, acc[p][0]);
                            acc[p][1] = fmaf(v, w1, acc[p][1]);
                            acc[p][2] = fmaf(v, w2, acc[p][2]);
                            acc[p][3] = fmaf(v, w3, acc[p][3]);
                        }
                }
            }
        }
        if (gimg < 8192) {
            #pragma unroll
            for (int cc = 0; cc < 4; cc++) {
                int ch = chunk + cg * 4 + cc;
                if (ch < 120) {
                    float b = c5_b[ch];
                    float4 o;
                    o.x = acc[0][cc] + b;
                    o.y = acc[1][cc] + b;
                    o.z = acc[2][cc] + b;
                    o.w = acc[3][cc] + b;
                    *(float4*)(outp + ch * 4) = o;
                }
            }
        }
    }
}

// ---------------------------------------------------------------------------
// K4: F6 (120->84) + act + RBF.  View C as [32768][120]; 64 rows/block.
// ---------------------------------------------------------------------------
#define K4_ROWS 64
#define K4_SMEM ((K4_ROWS * 121 + 120 * 84 + 840 + K4_ROWS * 85 + 84) * 4)

__global__ void __launch_bounds__(256) k4(const float* __restrict__ f6_w,
                                          const float* __restrict__ f6_b,
                                          const float* __restrict__ rbf_w,
                                          float* __restrict__ out) {
    extern __shared__ __align__(16) float sm4[];
    float* srow = sm4;                  // [64][121]
    float* swt  = srow + K4_ROWS * 121; // [120][84]  (k-major, pre-scaled)
    float* srbf = swt + 120 * 84;       // [84][10]
    float* sh   = srbf + 840;           // [64][85]
    float* sb6  = sh + K4_ROWS * 85;    // [84]       (pre-scaled)
    int t = threadIdx.x, blk = blockIdx.x;
    long row0 = (long)blk * K4_ROWS;

    for (int idx = t; idx < K4_ROWS * 120; idx += 256) {
        int r = idx / 120, k = idx % 120;
        srow[r * 121 + k] = g_C[(row0 + r) * 120 + k];
    }
    for (int idx = t; idx < 120 * 84; idx += 256) {
        int k = idx / 84, n = idx % 84;
        swt[idx] = ACT_SLOPE * f6_w[n * 120 + k];
    }
    for (int idx = t; idx < 840; idx += 256) srbf[idx] = rbf_w[idx];
    if (t < 84) sb6[t] = ACT_SLOPE * f6_b[t];
    __syncthreads();

    int rg = t >> 4;
    int cl = t & 15;
    float acc[4][6];
    #pragma unroll
    for (int i = 0; i < 4; i++)
        #pragma unroll
        for (int q = 0; q < 6; q++) acc[i][q] = 0.f;

    const float* r0 = srow + (rg * 4 + 0) * 121;
    const float* r1 = srow + (rg * 4 + 1) * 121;
    const float* r2 = srow + (rg * 4 + 2) * 121;
    const float* r3 = srow + (rg * 4 + 3) * 121;
    for (int k = 0; k < 120; k++) {
        float v0 = r0[k], v1 = r1[k], v2 = r2[k], v3 = r3[k];
        const float* wk = swt + k * 84;
        #pragma unroll
        for (int q = 0; q < 6; q++) {
            int n = cl + 16 * q;
            if (n < 84) {
                float w = wk[n];
                acc[0][q] = fmaf(v0, w, acc[0][q]);
                acc[1][q] = fmaf(v1, w, acc[1][q]);
                acc[2][q] = fmaf(v2, w, acc[2][q]);
                acc[3][q] = fmaf(v3, w, acc[3][q]);
            }
        }
    }
    #pragma unroll
    for (int q = 0; q < 6; q++) {
        int n = cl + 16 * q;
        if (n < 84) {
            float bias = sb6[n];
            #pragma unroll
            for (int i = 0; i < 4; i++)
                sh[(rg * 4 + i) * 85 + n] = ACT_SCALE * fast_tanh(acc[i][q] + bias);
        }
    }
    __syncthreads();

    for (int idx = t; idx < K4_ROWS * 10; idx += 256) {
        int r = idx / 10, o = idx % 10;
        const float* hr = sh + r * 85;
        float s = 0.f;
        #pragma unroll 4
        for (int n = 0; n < 84; n++) {
            float d = hr[n] - srbf[n * 10 + o];
            s = fmaf(d, d, s);
        }
        out[(row0 + r) * 10 + o] = s;
    }
}

// ---------------------------------------------------------------------------
extern "C" void kernel_launch(void* const* d_in, const int* in_sizes, int n_in,
                              void* d_out, int out_size) {
    const float* x     = (const float*)d_in[0];
    const float* c1_w  = (const float*)d_in[1];
    const float* c1_b  = (const float*)d_in[2];
    const float* s2_w  = (const float*)d_in[3];
    const float* s2_b  = (const float*)d_in[4];
    const float* c3_w  = (const float*)d_in[5];
    const float* c3_b  = (const float*)d_in[6];
    const float* s4_w  = (const float*)d_in[7];
    const float* s4_b  = (const float*)d_in[8];
    const float* c5_w  = (const float*)d_in[9];
    const float* c5_b  = (const float*)d_in[10];
    const float* f6_w  = (const float*)d_in[11];
    const float* f6_b  = (const float*)d_in[12];
    const float* rbf_w = (const float*)d_in[13];

    cudaFuncSetAttribute(k3, cudaFuncAttributeMaxDynamicSharedMemorySize, K3_SMEM);
    cudaFuncSetAttribute(k4, cudaFuncAttributeMaxDynamicSharedMemorySize, K4_SMEM);

    k_prep<<<1, 256>>>(c1_w, c1_b, s2_w, s2_b, c3_w, c3_b, s4_w, s4_b);
    k12<<<8192 / K12_IMG, K12_THREADS>>>(x);
    k3<<<K3_GRID, K3_THREADS, K3_SMEM>>>(c5_w, c5_b);
    k4<<<32768 / K4_ROWS, 256, K4_SMEM>>>(f6_w, f6_b, rbf_w, (float*)d_out);
}